// round 15
// baseline (speedup 1.0000x reference)
#include <cuda_runtime.h>
#include <cuda_fp16.h>
#include <math.h>
#include <stdint.h>

namespace {
constexpr int Bn  = 16;
constexpr int Cn  = 256;
constexpr int HWn = 4096;
constexpr int NHn = 8;
constexpr int Mn  = Bn * HWn;          // 65536 rows
constexpr float EPSF  = 1e-5f;
constexpr float SCALE = 0.17677669529663687f;  // 32^-0.5

constexpr int ROWB   = 80;             // bytes per 32-fp16 row in smem
constexpr int MATB   = 128 * ROWB;     // 10240 bytes per matrix tile
constexpr int STAGEB = 2 * MATB;       // A | B = 20480
constexpr int NSTAGE = 4;
constexpr int DYN_SMEM = NSTAGE * STAGEB;   // 81920 -> 2 CTAs/SM (160KB)
}

// ---------------- workspace (device globals; no allocation allowed) --------
__device__ __half g_T1 [(size_t)Mn * Cn];
__device__ __half g_T2 [(size_t)Mn * Cn];
__device__ __half g_P1 [(size_t)Mn * 2 * Cn];
__device__ __half g_P2 [(size_t)Mn * 2 * Cn];
__device__ __half g_KV1[(size_t)Mn * 2 * Cn];
__device__ __half g_KV2[(size_t)Mn * 2 * Cn];
__device__ float g_EP1[(size_t)Mn * Cn];
__device__ float g_EP2[(size_t)Mn * Cn];
__device__ __half g_MRG[(size_t)Mn * 2 * Cn];
__device__ float g_RES[(size_t)Mn * Cn];
__device__ __half g_CE [(size_t)Mn * Cn];
__device__ __half g_DW [(size_t)Mn * Cn];
__device__ float g_E  [(size_t)Mn * Cn];
__device__ float g_F  [(size_t)Mn * Cn];
__device__ __half g_WH[900000];
__device__ __half g_EPY[2 * 65536];
__device__ __half g_MW [2 * 16 * 65536];
__device__ float g_PART[(size_t)2 * Bn * NHn * 8 * 32 * 32];
__device__ float g_CTX1[(size_t)Bn * NHn * 32 * 32];
__device__ float g_CTX2[(size_t)Bn * NHn * 32 * 32];
__device__ float g_CB[512];
__device__ float g_BNP[1024 * 512];
__device__ float g_SC1[Cn];
__device__ float g_SH1[Cn];
__device__ float g_SC2[Cn];
__device__ float g_SH2[Cn];

// ---------------- PTX helpers ----------------------------------------------
__device__ __forceinline__ uint32_t smem_u32(const void* p) {
    uint32_t a;
    asm("{ .reg .u64 t; cvta.to.shared.u64 t, %1; cvt.u32.u64 %0, t; }"
        : "=r"(a) : "l"(p));
    return a;
}

__device__ __forceinline__ void cpasync16(uint32_t dst, const void* src) {
    asm volatile("cp.async.cg.shared.global [%0], [%1], 16;"
                 :: "r"(dst), "l"(src));
}

__device__ __forceinline__ void ldsm4(uint32_t* r, uint32_t addr) {
    asm volatile("ldmatrix.sync.aligned.m8n8.x4.shared.b16 {%0,%1,%2,%3}, [%4];"
                 : "=r"(r[0]), "=r"(r[1]), "=r"(r[2]), "=r"(r[3]) : "r"(addr));
}

__device__ __forceinline__ void mma16816(float* d, const uint32_t* a, const uint32_t* b) {
    asm volatile(
        "mma.sync.aligned.m16n8k16.row.col.f32.f16.f16.f32 "
        "{%0,%1,%2,%3}, {%4,%5,%6,%7}, {%8,%9}, {%0,%1,%2,%3};"
        : "+f"(d[0]), "+f"(d[1]), "+f"(d[2]), "+f"(d[3])
        : "r"(a[0]), "r"(a[1]), "r"(a[2]), "r"(a[3]), "r"(b[0]), "r"(b[1]));
}

// ---------------- preamble: weight converts + ep strided + bias concat ------
struct WsplitArgs {
    const float* src[7];   // cp1, cp2, kv1, kv2, res, ce1, ce3
};
__global__ void preamble_k(WsplitArgs a, const float* __restrict__ ep1_w,
                           const float* __restrict__ ep2_w, const float* __restrict__ ce1_b,
                           __half* __restrict__ h, __half* __restrict__ epy,
                           float* __restrict__ cb)
{
    const int i = blockIdx.x * 256 + threadIdx.x;
    if (i < 851968) {
        int seg, off;
        if (i < 786432) { seg = i >> 17; off = i & 131071; }
        else            { seg = 6;       off = i - 786432; }
        h[i] = __float2half(a.src[seg][off]);
    } else if (i < 983040) {
        const int j = i - 851968;
        const int path = j >> 16;
        const int rem  = j & 65535;
        const int o = rem >> 8, k = rem & 255;
        const float* w = path ? ep2_w : ep1_w;
        epy[j] = __float2half(w[o * 512 + k]);
    } else if (i < 983552) {
        const int t = i - 983040;
        cb[t] = (t < 256) ? 0.f : ce1_b[t - 256];
    }
}

// ---------------- transpose: x [B,C,HW] -> fp16 [B,HW,C] ---------------------
__global__ void transpose_split_k(const float* __restrict__ x1, const float* __restrict__ x2,
                                  __half* __restrict__ t1, __half* __restrict__ t2)
{
    __shared__ float s[32][33];
    const int z = blockIdx.z;
    const int path = z >> 4;
    const int b = z & 15;
    const float* x = path ? x2 : x1;
    __half* th = path ? t2 : t1;
    const int c0 = blockIdx.y * 32;
    const int n0 = blockIdx.x * 32;
    const float* xb = x + (size_t)b * Cn * HWn;
    const int tx = threadIdx.x, ty = threadIdx.y;  // 32 x 8
    #pragma unroll
    for (int i = 0; i < 32; i += 8)
        s[ty + i][tx] = xb[(size_t)(c0 + ty + i) * HWn + n0 + tx];
    __syncthreads();
    #pragma unroll
    for (int i = 0; i < 32; i += 8) {
        const size_t idx = ((size_t)b * HWn + n0 + ty + i) * Cn + c0 + tx;
        th[idx] = __float2half(s[tx][ty + i]);
    }
}

// ---------------- HMMA fp16 GEMM: 128x128 CTA, 4 warps, 64x64 warp tile ------
template<bool DUALB>
__device__ __forceinline__ void load_stage(
    uint32_t sb, int m0, int n0, int k0,
    const __half* A, int lda,
    const __half* W1, const __half* W2,
    int K, int tid)
{
    #pragma unroll
    for (int j = 0; j < 4; j++) {                       // A: 512 chunks / 128 thr
        const int idx = j * 128 + tid;
        const int r = idx >> 2, c = idx & 3;
        cpasync16(sb + r * ROWB + c * 16,
                  A + (size_t)(m0 + r) * lda + k0 + c * 8);
    }
    #pragma unroll
    for (int j = 0; j < 4; j++) {                       // B: 512 chunks / 128 thr
        const int idx = j * 128 + tid;
        const int r = idx >> 2, c = idx & 3;
        const uint32_t dst = sb + MATB + r * ROWB + c * 16;
        if (!DUALB) {
            cpasync16(dst, W1 + (size_t)(n0 + r) * K + k0 + c * 8);
        } else if (k0 < 256) {
            cpasync16(dst, W1 + (size_t)(n0 + r) * 256 + k0 + c * 8);
        } else {
            cpasync16(dst, W2 + (size_t)(n0 + r) * 256 + (k0 - 256) + c * 8);
        }
    }
}

// SPLIT: outF = fp32 [M,256] for cidx<256, outH = fp16 [M,256] for cidx>=256
// PAIR:  blockIdx.z selects pointer set 2
// BNS:   shuffle-reduced column partials (sum, sumsq) -> bnp, 2 segs per m-tile
template<bool BIAS, bool RELU, bool OUTF, bool OUTB, bool DUALB, bool SPLIT,
         bool PAIR, bool BNS>
__global__ void __launch_bounds__(128, 2)
gemm_tc(const __half* __restrict__ A, int lda,
        const __half* __restrict__ W1, const __half* __restrict__ W2,
        const float* __restrict__ bias,
        float* __restrict__ outF, __half* __restrict__ outH,
        const __half* A2, const __half* W1b, const __half* W2b,
        const float* bias2, float* outF2, __half* outH2,
        float* __restrict__ bnp,
        int K, int Nout)
{
    extern __shared__ char dyn_smem[];
    const int tid  = threadIdx.x;
    const int wid  = tid >> 5;
    const int lane = tid & 31;
    const int m0 = blockIdx.y * 128;
    const int n0 = blockIdx.x * 128;
    const int wm0 = (wid & 1) * 64;    // 2 warps over M
    const int wn0 = (wid >> 1) * 64;   // 2 warps over N

    if (PAIR && blockIdx.z == 1) {
        A = A2; W1 = W1b; W2 = W2b; bias = bias2; outF = outF2; outH = outH2;
    }
    if (DUALB) W2 += (size_t)(m0 >> 12) * 65536;

    const uint32_t base = smem_u32(dyn_smem);

    float acc[4][8][4];
    #pragma unroll
    for (int i = 0; i < 4; i++)
        #pragma unroll
        for (int j = 0; j < 8; j++)
            #pragma unroll
            for (int q = 0; q < 4; q++) acc[i][j][q] = 0.f;

    const uint32_t aOff = (uint32_t)(wm0 + (lane & 15)) * ROWB + ((lane >> 4) * 16);
    const uint32_t bOff = (uint32_t)(wn0 + ((lane >> 4) * 8) + (lane & 7)) * ROWB
                        + (((lane >> 3) & 1) * 16);

    const int S = K / 32;   // >= 8 for all our shapes
    load_stage<DUALB>(base, m0, n0, 0, A, lda, W1, W2, K, tid);
    asm volatile("cp.async.commit_group;" ::: "memory");
    load_stage<DUALB>(base + STAGEB, m0, n0, 32, A, lda, W1, W2, K, tid);
    asm volatile("cp.async.commit_group;" ::: "memory");
    load_stage<DUALB>(base + 2 * STAGEB, m0, n0, 64, A, lda, W1, W2, K, tid);
    asm volatile("cp.async.commit_group;" ::: "memory");

    int buf = 0;
    for (int s = 0; s < S; s++) {
        if (s + 3 <= S)
            asm volatile("cp.async.wait_group 2;" ::: "memory");
        else if (s + 2 <= S)
            asm volatile("cp.async.wait_group 1;" ::: "memory");
        else
            asm volatile("cp.async.wait_group 0;" ::: "memory");
        __syncthreads();
        if (s + 3 < S) {
            int nb = buf + 3; if (nb >= NSTAGE) nb -= NSTAGE;
            load_stage<DUALB>(base + nb * STAGEB, m0, n0, (s + 3) * 32,
                              A, lda, W1, W2, K, tid);
            asm volatile("cp.async.commit_group;" ::: "memory");
        }
        const uint32_t sb = base + buf * STAGEB;
        // load ALL fragments for both k-steps first (one stall window / stage)
        uint32_t bf0[4][4], af0[4][4], bf1[4][4], af1[4][4];
        #pragma unroll
        for (int np = 0; np < 4; np++)
            ldsm4(bf0[np], sb + MATB + bOff + np * 16 * ROWB);
        #pragma unroll
        for (int mi = 0; mi < 4; mi++)
            ldsm4(af0[mi], sb + aOff + mi * 16 * ROWB);
        #pragma unroll
        for (int np = 0; np < 4; np++)
            ldsm4(bf1[np], sb + MATB + bOff + np * 16 * ROWB + 32);
        #pragma unroll
        for (int mi = 0; mi < 4; mi++)
            ldsm4(af1[mi], sb + aOff + mi * 16 * ROWB + 32);
        #pragma unroll
        for (int mi = 0; mi < 4; mi++)
            #pragma unroll
            for (int ni = 0; ni < 8; ni++)
                mma16816(acc[mi][ni], af0[mi], &bf0[ni >> 1][(ni & 1) * 2]);
        #pragma unroll
        for (int mi = 0; mi < 4; mi++)
            #pragma unroll
            for (int ni = 0; ni < 8; ni++)
                mma16816(acc[mi][ni], af1[mi], &bf1[ni >> 1][(ni & 1) * 2]);
        buf++; if (buf >= NSTAGE) buf = 0;
    }

    // epilogue
    #pragma unroll
    for (int ni = 0; ni < 8; ni++) {
        const int cidx = n0 + wn0 + ni * 8 + (lane & 3) * 2;
        float b0 = 0.f, b1 = 0.f;
        if (BIAS) { b0 = bias[cidx]; b1 = bias[cidx + 1]; }
        float s0 = 0.f, s1 = 0.f, q0 = 0.f, q1 = 0.f;
        #pragma unroll
        for (int mi = 0; mi < 4; mi++) {
            const int r0 = m0 + wm0 + mi * 16 + (lane >> 2);
            #pragma unroll
            for (int half = 0; half < 2; half++) {
                const int r = r0 + half * 8;
                float v0 = acc[mi][ni][half * 2 + 0];
                float v1 = acc[mi][ni][half * 2 + 1];
                if (BIAS) { v0 += b0; v1 += b1; }
                if (RELU) { v0 = fmaxf(v0, 0.f); v1 = fmaxf(v1, 0.f); }
                if (BNS) {
                    s0 += v0; s1 += v1;
                    q0 = fmaf(v0, v0, q0); q1 = fmaf(v1, v1, q1);
                }
                if (SPLIT) {
                    if (cidx < 256) {
                        float2 f2 = make_float2(v0, v1);
                        *reinterpret_cast<float2*>(outF + (size_t)r * 256 + cidx) = f2;
                    } else {
                        __half2 hh = __halves2half2(__float2half(v0), __float2half(v1));
                        *reinterpret_cast<__half2*>(outH + (size_t)r * 256 + cidx - 256) = hh;
                    }
                } else {
                    if (OUTF) {
                        float2 f2 = make_float2(v0, v1);
                        *reinterpret_cast<float2*>(outF + (size_t)r * Nout + cidx) = f2;
                    }
                    if (OUTB) {
                        __half2 hh = __halves2half2(__float2half(v0), __float2half(v1));
                        *reinterpret_cast<__half2*>(outH + (size_t)r * Nout + cidx) = hh;
                    }
                }
            }
        }
        if (BNS) {
            // reduce over the 8 lanes covering this warp's 64 rows (stride-4 groups)
            #pragma unroll
            for (int off = 4; off < 32; off <<= 1) {
                s0 += __shfl_xor_sync(0xffffffffu, s0, off);
                s1 += __shfl_xor_sync(0xffffffffu, s1, off);
                q0 += __shfl_xor_sync(0xffffffffu, q0, off);
                q1 += __shfl_xor_sync(0xffffffffu, q1, off);
            }
            if ((lane >> 2) == 0) {
                const int seg = blockIdx.y * 2 + (wid & 1);
                bnp[seg * 512 + cidx]           = s0;
                bnp[seg * 512 + cidx + 1]       = s1;
                bnp[seg * 512 + 256 + cidx]     = q0;
                bnp[seg * 512 + 256 + cidx + 1] = q1;
            }
        }
    }
}

// ------------- ctx partial: per (chunk,h,b,path) K^T V over 512 rows --------
__global__ void __launch_bounds__(64)
ctx_partial_k(const __half* __restrict__ KV1, const __half* __restrict__ KV2,
              float* __restrict__ part)
{
    __shared__ float Ks[64][32];
    __shared__ float Vs[64][32];
    const int chunk = blockIdx.x, h = blockIdx.y, z = blockIdx.z;
    const int b = z & 15;
    const __half* KV = (z < 16) ? KV1 : KV2;
    const int t = threadIdx.x, lane = t & 31, w = t >> 5;
    const __half* base = KV + (size_t)b * HWn * 512;
    const int d0 = (t >> 3) * 4, e0 = (t & 7) * 4;
    float acc[4][4] = {};
    for (int nb = 0; nb < 512; nb += 64) {
        const int row0 = chunk * 512 + nb;
        for (int r = w; r < 64; r += 2) {
            const __half* rp = base + (size_t)(row0 + r) * 512 + h * 32;
            Ks[r][lane] = __half2float(rp[lane]);
            Vs[r][lane] = __half2float(rp[256 + lane]);
        }
        __syncthreads();
        #pragma unroll 8
        for (int n = 0; n < 64; n++) {
            float4 k4 = *reinterpret_cast<float4*>(&Ks[n][d0]);
            float4 v4 = *reinterpret_cast<float4*>(&Vs[n][e0]);
            const float kk[4] = {k4.x, k4.y, k4.z, k4.w};
            const float vv[4] = {v4.x, v4.y, v4.z, v4.w};
            #pragma unroll
            for (int i = 0; i < 4; i++)
                #pragma unroll
                for (int j = 0; j < 4; j++)
                    acc[i][j] = fmaf(kk[i], vv[j], acc[i][j]);
        }
        __syncthreads();
    }
    float* p = part + ((size_t)(z * NHn + h) * 8 + chunk) * 1024;
    #pragma unroll
    for (int i = 0; i < 4; i++)
        #pragma unroll
        for (int j = 0; j < 4; j++)
            p[(d0 + i) * 32 + e0 + j] = acc[i][j];
}

// ------------- ctx finalize: sum partials, scale, softmax over d -----------
__global__ void ctx_final_k(const float* __restrict__ part, float* __restrict__ ctx1,
                            float* __restrict__ ctx2)
{
    __shared__ float S[32][33];
    const int bhg = blockIdx.x;        // [0,256): path*128 + bh
    float* ctx = (bhg < 128) ? ctx1 : ctx2;
    const int bh = bhg & 127;
    const int t  = threadIdx.x;
    const float* p = part + (size_t)bhg * 8 * 1024;
    for (int idx = t; idx < 1024; idx += 256) {
        float s = 0.f;
        #pragma unroll
        for (int c = 0; c < 8; c++) s += p[c * 1024 + idx];
        S[idx >> 5][idx & 31] = s * SCALE;
    }
    __syncthreads();
    if (t < 32) {
        float mx = -1e30f;
        #pragma unroll
        for (int d = 0; d < 32; d++) mx = fmaxf(mx, S[d][t]);
        float e[32], sum = 0.f;
        #pragma unroll
        for (int d = 0; d < 32; d++) { e[d] = expf(S[d][t] - mx); sum += e[d]; }
        const float inv = 1.f / sum;
        float* o = ctx + (size_t)bh * 1024;
        #pragma unroll
        for (int d = 0; d < 32; d++) o[d * 32 + t] = e[d] * inv;
    }
}

// ------------- build per-batch ep "M" weights: M[o, j] (fp16) ---------------
__global__ void __launch_bounds__(256)
ctxw_k(const float* __restrict__ ctx1, const float* __restrict__ ctx2,
       const float* __restrict__ ep1_w, const float* __restrict__ ep2_w,
       __half* __restrict__ mw)
{
    __shared__ float cs[8192];
    const int z = blockIdx.x;                 // path*16 + b
    const int og = blockIdx.y;                // o-group: 16 o values
    const int path = z >> 4;
    const int b = z & 15;
    const float* ctx = path ? ctx1 : ctx2;
    const float* epw = path ? ep2_w : ep1_w;
    const int j = threadIdx.x;                // u-column 0..255
    for (int i = j; i < 8192; i += 256)
        cs[i] = ctx[(size_t)b * 8192 + i];
    __syncthreads();
    const int h = j >> 5, d = j & 31;
    float c[32];
    #pragma unroll
    for (int e = 0; e < 32; e++) c[e] = cs[h * 1024 + d * 32 + e];
    __half* oh = mw + (size_t)z * 65536;
    #pragma unroll
    for (int oo = 0; oo < 16; oo++) {
        const int o = og * 16 + oo;
        const float* wr = epw + (size_t)o * 512 + 256 + h * 32;
        float a = 0.f;
        #pragma unroll
        for (int e = 0; e < 32; e++) a = fmaf(c[e], __ldg(wr + e), a);
        oh[o * 256 + j] = __float2half(a);
    }
}

// ------------- LayerNorm: MRG[:, mco..] = LN(T + EP)*g + b (fp16 out) --------
__global__ void __launch_bounds__(256)
ln_k(const __half* __restrict__ T1, const __half* __restrict__ T2,
     const float* __restrict__ EP1, const float* __restrict__ EP2,
     const float* __restrict__ g1, const float* __restrict__ b1,
     const float* __restrict__ g2, const float* __restrict__ b2,
     __half* __restrict__ MH)
{
    const int path = blockIdx.y;
    const __half* Th = path ? T2 : T1;
    const float* EP = path ? EP2 : EP1;
    const float* g  = path ? g2 : g1;
    const float* be = path ? b2 : b1;
    const int mco = path * 256;
    const int w    = blockIdx.x * 8 + (threadIdx.x >> 5);
    const int lane = threadIdx.x & 31;
    const __half* th = Th + (size_t)w * 256;
    const float* er = EP + (size_t)w * 256;
    float v[8], sum = 0.f, sq = 0.f;
    #pragma unroll
    for (int i = 0; i < 8; i++) {
        const int c = lane + i * 32;
        const float x = __half2float(th[c]) + er[c];
        v[i] = x; sum += x; sq += x * x;
    }
    #pragma unroll
    for (int o = 16; o; o >>= 1) {
        sum += __shfl_xor_sync(0xffffffffu, sum, o);
        sq  += __shfl_xor_sync(0xffffffffu, sq,  o);
    }
    const float mean = sum * (1.f / 256.f);
    const float var  = sq * (1.f / 256.f) - mean * mean;
    const float rs   = rsqrtf(var + EPSF);
    const size_t ob = (size_t)w * 512 + mco;
    #pragma unroll
    for (int i = 0; i < 8; i++) {
        const int c = lane + i * 32;
        MH[ob + c] = __float2half((v[i] - mean) * rs * g[c] + be[c]);
    }
}

// ------------- 3x3 depthwise conv on fp16 [M,256] + bias + relu (fp16 out) ---
__global__ void __launch_bounds__(256)
dw_k(const __half* __restrict__ X, const float* __restrict__ w9,
     const float* __restrict__ db, __half* __restrict__ Y)
{
    __shared__ float s[18 * 18 * 32];
    const int cc   = blockIdx.x;
    const int tile = blockIdx.y;
    const int b    = blockIdx.z;
    const int ty0 = (tile >> 2) * 16, tx0 = (tile & 3) * 16;
    const int c0 = cc * 32;
    const int tid = threadIdx.x;
    for (int i = tid; i < 18 * 18 * 32; i += 256) {
        const int c = i & 31;
        const int sp = i >> 5;
        const int x = sp % 18 - 1 + tx0;
        const int y = sp / 18 - 1 + ty0;
        float v = 0.f;
        if (x >= 0 && x < 64 && y >= 0 && y < 64)
            v = __half2float(X[(size_t)(b * 4096 + y * 64 + x) * 256 + c0 + c]);
        s[i] = v;
    }
    const int c = tid & 31;
    float kr[9];
    #pragma unroll
    for (int j = 0; j < 9; j++) kr[j] = w9[(c0 + c) * 9 + j];
    const float bb = db[c0 + c];
    __syncthreads();
    for (int o = tid; o < 8192; o += 256) {
        const int sp = o >> 5;
        const int x = sp & 15, y = sp >> 4;
        float a = 0.f;
        #pragma unroll
        for (int dy = 0; dy < 3; dy++)
            #pragma unroll
            for (int dx = 0; dx < 3; dx++)
                a = fmaf(s[((y + dy) * 18 + (x + dx)) * 32 + c], kr[dy * 3 + dx], a);
        a = fmaxf(a + bb, 0.f);
        const size_t idx = (size_t)(b * 4096 + (ty0 + y) * 64 + tx0 + x) * 256 + c0 + c;
        Y[idx] = __float2half(a);
    }
}

// ------------- bn finalize from partials (1024 threads, 4-way split) ---------
__global__ void __launch_bounds__(1024)
bn_fin_k(const float* __restrict__ part, int nseg,
         const float* __restrict__ g, const float* __restrict__ be,
         float* __restrict__ sc, float* __restrict__ sh)
{
    __shared__ float ss[4][256];
    __shared__ float sq[4][256];
    const int c = threadIdx.x & 255;
    const int q = threadIdx.x >> 8;     // 0..3
    float s = 0.f, qq = 0.f;
    for (int seg = q; seg < nseg; seg += 4) {
        s  += part[seg * 512 + c];
        qq += part[seg * 512 + 256 + c];
    }
    ss[q][c] = s; sq[q][c] = qq;
    __syncthreads();
    if (q == 0) {
        s  = ss[0][c] + ss[1][c] + ss[2][c] + ss[3][c];
        qq = sq[0][c] + sq[1][c] + sq[2][c] + sq[3][c];
        const float inv = 1.f / 65536.f;
        const float m   = s * inv;
        const float var = qq * inv - m * m;
        const float scv = g[c] * rsqrtf(var + EPSF);
        sc[c] = scv;
        sh[c] = be[c] - m * scv;
    }
}

// ------------- F = RES + E*sc + sh, fused with F column partials -------------
__global__ void __launch_bounds__(256)
addbn_bn_k(const float* __restrict__ RES, const float* __restrict__ E,
           const float* __restrict__ sc, const float* __restrict__ sh,
           float* __restrict__ F, float* __restrict__ part)
{
    const int seg = blockIdx.x;          // 256 segments of 256 rows
    const int c   = threadIdx.x;
    const float s = sc[c], hh = sh[c];
    const size_t base = (size_t)seg * 256 * 256;
    float su = 0.f, q = 0.f;
    #pragma unroll 4
    for (int r = 0; r < 256; r++) {
        const size_t idx = base + (size_t)r * 256 + c;
        const float f = fmaf(E[idx], s, RES[idx] + hh);
        F[idx] = f;
        su += f;
        q = fmaf(f, f, q);
    }
    part[seg * 512 + c] = su;
    part[seg * 512 + 256 + c] = q;
}

// ------------- final: out NCHW = bn2(F) via transpose ------------------------
__global__ void bn_final_k(const float* __restrict__ F, const float* __restrict__ sc,
                           const float* __restrict__ sh, float* __restrict__ O)
{
    __shared__ float s[32][33];
    const int b  = blockIdx.z;
    const int c0 = blockIdx.y * 32;
    const int n0 = blockIdx.x * 32;
    const int tx = threadIdx.x, ty = threadIdx.y;
    #pragma unroll
    for (int i = 0; i < 32; i += 8)
        s[ty + i][tx] = F[((size_t)(b * 4096 + n0 + ty + i)) * 256 + c0 + tx];
    __syncthreads();
    #pragma unroll
    for (int i = 0; i < 32; i += 8) {
        const int c = c0 + ty + i;
        O[((size_t)(b * 256 + c)) * 4096 + n0 + tx] = s[tx][ty + i] * sc[c] + sh[c];
    }
}

// ===========================================================================
extern "C" void kernel_launch(void* const* d_in, const int* in_sizes, int n_in,
                              void* d_out, int out_size)
{
    (void)in_sizes; (void)n_in; (void)out_size;
    const float* x1    = (const float*)d_in[0];
    const float* x2    = (const float*)d_in[1];
    const float* cp1_w = (const float*)d_in[2];
    const float* cp1_b = (const float*)d_in[3];
    const float* cp2_w = (const float*)d_in[4];
    const float* cp2_b = (const float*)d_in[5];
    const float* kv1_w = (const float*)d_in[6];
    const float* kv2_w = (const float*)d_in[7];
    const float* ep1_w = (const float*)d_in[8];
    const float* ep1_b = (const float*)d_in[9];
    const float* ep2_w = (const float*)d_in[10];
    const float* ep2_b = (const float*)d_in[11];
    const float* ln1_g = (const float*)d_in[12];
    const float* ln1_b = (const float*)d_in[13];
    const float* ln2_g = (const float*)d_in[14];
    const float* ln2_b = (const float*)d_in[15];
    const float* res_w = (const float*)d_in[16];
    const float* ce1_w = (const float*)d_in[17];
    const float* ce1_b = (const float*)d_in[18];
    const float* dw_w  = (const float*)d_in[19];
    const float* dw_b  = (const float*)d_in[20];
    const float* ce3_w = (const float*)d_in[21];
    const float* ce3_b = (const float*)d_in[22];
    const float* bn1_g = (const float*)d_in[23];
    const float* bn1_b = (const float*)d_in[24];
    const float* bn2_g = (const float*)d_in[25];
    const float* bn2_b = (const float*)d_in[26];

    float *EP1, *EP2, *RES, *E, *F;
    float *PART, *CTX1, *CTX2, *CB, *BNP, *SC1, *SH1, *SC2, *SH2;
    __half *T1, *T2, *P1, *P2, *KV1, *KV2, *MRG, *CE, *DW, *WH, *EPY, *MW;
    cudaGetSymbolAddress((void**)&T1,  g_T1);
    cudaGetSymbolAddress((void**)&T2,  g_T2);
    cudaGetSymbolAddress((void**)&P1,  g_P1);
    cudaGetSymbolAddress((void**)&P2,  g_P2);
    cudaGetSymbolAddress((void**)&KV1, g_KV1);
    cudaGetSymbolAddress((void**)&KV2, g_KV2);
    cudaGetSymbolAddress((void**)&EP1, g_EP1);
    cudaGetSymbolAddress((void**)&EP2, g_EP2);
    cudaGetSymbolAddress((void**)&MRG, g_MRG);
    cudaGetSymbolAddress((void**)&RES, g_RES);
    cudaGetSymbolAddress((void**)&CE,  g_CE);
    cudaGetSymbolAddress((void**)&DW,  g_DW);
    cudaGetSymbolAddress((void**)&E,   g_E);
    cudaGetSymbolAddress((void**)&F,   g_F);
    cudaGetSymbolAddress((void**)&WH,  g_WH);
    cudaGetSymbolAddress((void**)&EPY, g_EPY);
    cudaGetSymbolAddress((void**)&MW,  g_MW);
    cudaGetSymbolAddress((void**)&PART, g_PART);
    cudaGetSymbolAddress((void**)&CTX1, g_CTX1);
    cudaGetSymbolAddress((void**)&CTX2, g_CTX2);
    cudaGetSymbolAddress((void**)&CB,  g_CB);
    cudaGetSymbolAddress((void**)&BNP, g_BNP);
    cudaGetSymbolAddress((void**)&SC1, g_SC1);
    cudaGetSymbolAddress((void**)&SH1, g_SH1);
    cudaGetSymbolAddress((void**)&SC2, g_SC2);
    cudaGetSymbolAddress((void**)&SH2, g_SH2);

    cudaFuncSetAttribute(gemm_tc<true,  true,  false, true , false, false, true , false>,
                         cudaFuncAttributeMaxDynamicSharedMemorySize, DYN_SMEM);
    cudaFuncSetAttribute(gemm_tc<false, false, false, true , false, false, true , false>,
                         cudaFuncAttributeMaxDynamicSharedMemorySize, DYN_SMEM);
    cudaFuncSetAttribute(gemm_tc<true,  false, true,  false, true , false, true , false>,
                         cudaFuncAttributeMaxDynamicSharedMemorySize, DYN_SMEM);
    cudaFuncSetAttribute(gemm_tc<true,  false, false, false, false, true , false, false>,
                         cudaFuncAttributeMaxDynamicSharedMemorySize, DYN_SMEM);
    cudaFuncSetAttribute(gemm_tc<true,  false, true,  false, false, false, false, true >,
                         cudaFuncAttributeMaxDynamicSharedMemorySize, DYN_SMEM);

    // weight slots in WH (851968 total)
    const size_t oCP1 = 0, oCP2 = 131072, oKV1 = 262144, oKV2 = 393216;
    const size_t oRC = 524288, oCE3 = 786432;
    WsplitArgs wa;
    wa.src[0] = cp1_w; wa.src[1] = cp2_w; wa.src[2] = kv1_w; wa.src[3] = kv2_w;
    wa.src[4] = res_w; wa.src[5] = ce1_w; wa.src[6] = ce3_w;

    // merged preamble: weight converts + ep strided + bias concat
    preamble_k<<<3842, 256>>>(wa, ep1_w, ep2_w, ce1_b, WH, EPY, CB);
    transpose_split_k<<<dim3(128, 8, 32), dim3(32, 8)>>>(x1, x2, T1, T2);

    // CrossPath pair: P = relu(T @ cp_w^T + b) -> fp16
    gemm_tc<true, true, false, true, false, false, true, false>
        <<<dim3(4, 512, 2), 128, DYN_SMEM>>>(
        T1, 256, WH + oCP1, nullptr, cp1_b, nullptr, P1,
        T2, WH + oCP2, nullptr, cp2_b, nullptr, P2, nullptr, 256, 512);

    // KV pair: KV = u @ kv_w^T -> fp16
    gemm_tc<false, false, false, true, false, false, true, false>
        <<<dim3(4, 512, 2), 128, DYN_SMEM>>>(
        P1 + 256, 512, WH + oKV1, nullptr, nullptr, nullptr, KV1,
        P2 + 256, WH + oKV2, nullptr, nullptr, nullptr, KV2, nullptr, 256, 512);

    // ctx = softmax_d(scale * K^T V), both paths
    ctx_partial_k<<<dim3(8, 8, 32), 64>>>(KV1, KV2, PART);
    ctx_final_k<<<256, 256>>>(PART, CTX1, CTX2);

    // per-batch M weights for the fused ep GEMM (cross-wired)
    ctxw_k<<<dim3(32, 16), 256>>>(CTX1, CTX2, ep1_w, ep2_w, MW);

    // EP pair: EP = y @ W1 + u @ M_b + bias (dual-source B)
    gemm_tc<true, false, true, false, true, false, true, false>
        <<<dim3(2, 512, 2), 128, DYN_SMEM>>>(
        P1, 512, EPY, MW, ep1_b, EP1, nullptr,
        P2, EPY + 65536, MW + 16 * 65536, ep2_b, EP2, nullptr, nullptr, 512, 256);

    // LN both paths -> MRG fp16
    ln_k<<<dim3(8192, 2), 256>>>(T1, T2, EP1, EP2,
                                 ln1_g, ln1_b, ln2_g, ln2_b, MRG);

    // res|ce1 concatenated GEMM -> RES fp32 [M,256] + CE fp16 [M,256]
    gemm_tc<true, false, false, false, false, true, false, false>
        <<<dim3(4, 512), 128, DYN_SMEM>>>(
        MRG, 512, WH + oRC, nullptr, CB, RES, CE,
        nullptr, nullptr, nullptr, nullptr, nullptr, nullptr, nullptr, 512, 512);

    // 3x3 depthwise (+bias+relu) on fp16 CE -> DW fp16
    dw_k<<<dim3(8, 16, 16), 256>>>(CE, dw_w, dw_b, DW);

    // ce3 GEMM -> E fp32, bn1 column partials via warp shuffles (no atomics)
    gemm_tc<true, false, true, false, false, false, false, true>
        <<<dim3(2, 512), 128, DYN_SMEM>>>(
        DW, 256, WH + oCE3, nullptr, ce3_b, E, nullptr,
        nullptr, nullptr, nullptr, nullptr, nullptr, nullptr, BNP, 256, 256);

    // bn1 finalize -> fused residual add + bn1 apply + bn2 partials -> bn2 -> out
    bn_fin_k<<<1, 1024>>>(BNP, 1024, bn1_g, bn1_b, SC1, SH1);
    addbn_bn_k<<<256, 256>>>(RES, E, SC1, SH1, F, BNP);
    bn_fin_k<<<1, 1024>>>(BNP, 256, bn2_g, bn2_b, SC2, SH2);
    bn_final_k<<<dim3(128, 8, 16), dim3(32, 8)>>>(F, SC2, SH2, (float*)d_out);
}

// round 16
// speedup vs baseline: 1.0008x; 1.0008x over previous
#include <cuda_runtime.h>
#include <cuda_fp16.h>
#include <math.h>
#include <stdint.h>

namespace {
constexpr int Bn  = 16;
constexpr int Cn  = 256;
constexpr int HWn = 4096;
constexpr int NHn = 8;
constexpr int Mn  = Bn * HWn;          // 65536 rows
constexpr float EPSF  = 1e-5f;
constexpr float SCALE = 0.17677669529663687f;  // 32^-0.5

constexpr int ROWB   = 80;             // bytes per 32-fp16 row in smem
constexpr int MATB   = 128 * ROWB;     // 10240 bytes per matrix tile
constexpr int STAGEB = 2 * MATB;       // A | B = 20480
constexpr int NSTAGE = 4;
constexpr int DYN_SMEM = NSTAGE * STAGEB;   // 81920 -> 2 CTAs/SM (160KB)
}

// ---------------- workspace (device globals; no allocation allowed) --------
__device__ __half g_T1 [(size_t)Mn * Cn];
__device__ __half g_T2 [(size_t)Mn * Cn];
__device__ __half g_P1 [(size_t)Mn * 2 * Cn];
__device__ __half g_P2 [(size_t)Mn * 2 * Cn];
__device__ __half g_KV1[(size_t)Mn * 2 * Cn];
__device__ __half g_KV2[(size_t)Mn * 2 * Cn];
__device__ float g_EP1[(size_t)Mn * Cn];
__device__ float g_EP2[(size_t)Mn * Cn];
__device__ __half g_MRG[(size_t)Mn * 2 * Cn];
__device__ float g_RES[(size_t)Mn * Cn];
__device__ __half g_CE [(size_t)Mn * Cn];
__device__ __half g_DW [(size_t)Mn * Cn];
__device__ float g_E  [(size_t)Mn * Cn];
__device__ float g_F  [(size_t)Mn * Cn];
__device__ __half g_WH[900000];
__device__ __half g_EPY[2 * 65536];
__device__ __half g_MW [2 * 16 * 65536];
__device__ float g_PART[(size_t)2 * Bn * NHn * 8 * 32 * 32];
__device__ float g_CTX1[(size_t)Bn * NHn * 32 * 32];
__device__ float g_CTX2[(size_t)Bn * NHn * 32 * 32];
__device__ float g_CB[512];
__device__ float g_BNP[1024 * 512];
__device__ float g_SC1[Cn];
__device__ float g_SH1[Cn];
__device__ float g_SC2[Cn];
__device__ float g_SH2[Cn];

// ---------------- PTX helpers ----------------------------------------------
__device__ __forceinline__ uint32_t smem_u32(const void* p) {
    uint32_t a;
    asm("{ .reg .u64 t; cvta.to.shared.u64 t, %1; cvt.u32.u64 %0, t; }"
        : "=r"(a) : "l"(p));
    return a;
}

__device__ __forceinline__ void cpasync16(uint32_t dst, const void* src) {
    asm volatile("cp.async.cg.shared.global [%0], [%1], 16;"
                 :: "r"(dst), "l"(src));
}

__device__ __forceinline__ void ldsm4(uint32_t* r, uint32_t addr) {
    asm volatile("ldmatrix.sync.aligned.m8n8.x4.shared.b16 {%0,%1,%2,%3}, [%4];"
                 : "=r"(r[0]), "=r"(r[1]), "=r"(r[2]), "=r"(r[3]) : "r"(addr));
}

__device__ __forceinline__ void mma16816(float* d, const uint32_t* a, const uint32_t* b) {
    asm volatile(
        "mma.sync.aligned.m16n8k16.row.col.f32.f16.f16.f32 "
        "{%0,%1,%2,%3}, {%4,%5,%6,%7}, {%8,%9}, {%0,%1,%2,%3};"
        : "+f"(d[0]), "+f"(d[1]), "+f"(d[2]), "+f"(d[3])
        : "r"(a[0]), "r"(a[1]), "r"(a[2]), "r"(a[3]), "r"(b[0]), "r"(b[1]));
}

// ---------------- preamble: weight converts + ep strided + bias concat ------
struct WsplitArgs {
    const float* src[7];   // cp1, cp2, kv1, kv2, res, ce1, ce3
};
__global__ void preamble_k(WsplitArgs a, const float* __restrict__ ep1_w,
                           const float* __restrict__ ep2_w, const float* __restrict__ ce1_b,
                           __half* __restrict__ h, __half* __restrict__ epy,
                           float* __restrict__ cb)
{
    const int i = blockIdx.x * 256 + threadIdx.x;
    if (i < 851968) {
        int seg, off;
        if (i < 786432) { seg = i >> 17; off = i & 131071; }
        else            { seg = 6;       off = i - 786432; }
        h[i] = __float2half(a.src[seg][off]);
    } else if (i < 983040) {
        const int j = i - 851968;
        const int path = j >> 16;
        const int rem  = j & 65535;
        const int o = rem >> 8, k = rem & 255;
        const float* w = path ? ep2_w : ep1_w;
        epy[j] = __float2half(w[o * 512 + k]);
    } else if (i < 983552) {
        const int t = i - 983040;
        cb[t] = (t < 256) ? 0.f : ce1_b[t - 256];
    }
}

// ---------------- transpose: x [B,C,HW] -> fp16 [B,HW,C] ---------------------
__global__ void transpose_split_k(const float* __restrict__ x1, const float* __restrict__ x2,
                                  __half* __restrict__ t1, __half* __restrict__ t2)
{
    __shared__ float s[32][33];
    const int z = blockIdx.z;
    const int path = z >> 4;
    const int b = z & 15;
    const float* x = path ? x2 : x1;
    __half* th = path ? t2 : t1;
    const int c0 = blockIdx.y * 32;
    const int n0 = blockIdx.x * 32;
    const float* xb = x + (size_t)b * Cn * HWn;
    const int tx = threadIdx.x, ty = threadIdx.y;  // 32 x 8
    #pragma unroll
    for (int i = 0; i < 32; i += 8)
        s[ty + i][tx] = xb[(size_t)(c0 + ty + i) * HWn + n0 + tx];
    __syncthreads();
    #pragma unroll
    for (int i = 0; i < 32; i += 8) {
        const size_t idx = ((size_t)b * HWn + n0 + ty + i) * Cn + c0 + tx;
        th[idx] = __float2half(s[tx][ty + i]);
    }
}

// ---------------- HMMA fp16 GEMM: 128x128 CTA, 4 warps, 64x64 warp tile ------
template<bool DUALB>
__device__ __forceinline__ void load_stage(
    uint32_t sb, int m0, int n0, int k0,
    const __half* A, int lda,
    const __half* W1, const __half* W2,
    int K, int tid)
{
    #pragma unroll
    for (int j = 0; j < 4; j++) {                       // A: 512 chunks / 128 thr
        const int idx = j * 128 + tid;
        const int r = idx >> 2, c = idx & 3;
        cpasync16(sb + r * ROWB + c * 16,
                  A + (size_t)(m0 + r) * lda + k0 + c * 8);
    }
    #pragma unroll
    for (int j = 0; j < 4; j++) {                       // B: 512 chunks / 128 thr
        const int idx = j * 128 + tid;
        const int r = idx >> 2, c = idx & 3;
        const uint32_t dst = sb + MATB + r * ROWB + c * 16;
        if (!DUALB) {
            cpasync16(dst, W1 + (size_t)(n0 + r) * K + k0 + c * 8);
        } else if (k0 < 256) {
            cpasync16(dst, W1 + (size_t)(n0 + r) * 256 + k0 + c * 8);
        } else {
            cpasync16(dst, W2 + (size_t)(n0 + r) * 256 + (k0 - 256) + c * 8);
        }
    }
}

// SPLIT: outF = fp32 [M,256] for cidx<256, outH = fp16 [M,256] for cidx>=256
// PAIR:  blockIdx.z selects pointer set 2
// BNS:   shuffle-reduced column partials (sum, sumsq) -> bnp, 2 segs per m-tile
template<bool BIAS, bool RELU, bool OUTF, bool OUTB, bool DUALB, bool SPLIT,
         bool PAIR, bool BNS>
__global__ void __launch_bounds__(128, 2)
gemm_tc(const __half* __restrict__ A, int lda,
        const __half* __restrict__ W1, const __half* __restrict__ W2,
        const float* __restrict__ bias,
        float* __restrict__ outF, __half* __restrict__ outH,
        const __half* A2, const __half* W1b, const __half* W2b,
        const float* bias2, float* outF2, __half* outH2,
        float* __restrict__ bnp,
        int K, int Nout)
{
    extern __shared__ char dyn_smem[];
    const int tid  = threadIdx.x;
    const int wid  = tid >> 5;
    const int lane = tid & 31;
    const int m0 = blockIdx.y * 128;
    const int n0 = blockIdx.x * 128;
    const int wm0 = (wid & 1) * 64;    // 2 warps over M
    const int wn0 = (wid >> 1) * 64;   // 2 warps over N

    if (PAIR && blockIdx.z == 1) {
        A = A2; W1 = W1b; W2 = W2b; bias = bias2; outF = outF2; outH = outH2;
    }
    if (DUALB) W2 += (size_t)(m0 >> 12) * 65536;

    const uint32_t base = smem_u32(dyn_smem);

    float acc[4][8][4];
    #pragma unroll
    for (int i = 0; i < 4; i++)
        #pragma unroll
        for (int j = 0; j < 8; j++)
            #pragma unroll
            for (int q = 0; q < 4; q++) acc[i][j][q] = 0.f;

    const uint32_t aOff = (uint32_t)(wm0 + (lane & 15)) * ROWB + ((lane >> 4) * 16);
    const uint32_t bOff = (uint32_t)(wn0 + ((lane >> 4) * 8) + (lane & 7)) * ROWB
                        + (((lane >> 3) & 1) * 16);

    const int S = K / 32;   // >= 8 for all our shapes
    load_stage<DUALB>(base, m0, n0, 0, A, lda, W1, W2, K, tid);
    asm volatile("cp.async.commit_group;" ::: "memory");
    load_stage<DUALB>(base + STAGEB, m0, n0, 32, A, lda, W1, W2, K, tid);
    asm volatile("cp.async.commit_group;" ::: "memory");
    load_stage<DUALB>(base + 2 * STAGEB, m0, n0, 64, A, lda, W1, W2, K, tid);
    asm volatile("cp.async.commit_group;" ::: "memory");

    int buf = 0;
    for (int s = 0; s < S; s++) {
        if (s + 3 <= S)
            asm volatile("cp.async.wait_group 2;" ::: "memory");
        else if (s + 2 <= S)
            asm volatile("cp.async.wait_group 1;" ::: "memory");
        else
            asm volatile("cp.async.wait_group 0;" ::: "memory");
        __syncthreads();
        if (s + 3 < S) {
            int nb = buf + 3; if (nb >= NSTAGE) nb -= NSTAGE;
            load_stage<DUALB>(base + nb * STAGEB, m0, n0, (s + 3) * 32,
                              A, lda, W1, W2, K, tid);
            asm volatile("cp.async.commit_group;" ::: "memory");
        }
        const uint32_t sb = base + buf * STAGEB;
        // load ALL fragments for both k-steps first (one stall window / stage)
        uint32_t bf0[4][4], af0[4][4], bf1[4][4], af1[4][4];
        #pragma unroll
        for (int np = 0; np < 4; np++)
            ldsm4(bf0[np], sb + MATB + bOff + np * 16 * ROWB);
        #pragma unroll
        for (int mi = 0; mi < 4; mi++)
            ldsm4(af0[mi], sb + aOff + mi * 16 * ROWB);
        #pragma unroll
        for (int np = 0; np < 4; np++)
            ldsm4(bf1[np], sb + MATB + bOff + np * 16 * ROWB + 32);
        #pragma unroll
        for (int mi = 0; mi < 4; mi++)
            ldsm4(af1[mi], sb + aOff + mi * 16 * ROWB + 32);
        #pragma unroll
        for (int mi = 0; mi < 4; mi++)
            #pragma unroll
            for (int ni = 0; ni < 8; ni++)
                mma16816(acc[mi][ni], af0[mi], &bf0[ni >> 1][(ni & 1) * 2]);
        #pragma unroll
        for (int mi = 0; mi < 4; mi++)
            #pragma unroll
            for (int ni = 0; ni < 8; ni++)
                mma16816(acc[mi][ni], af1[mi], &bf1[ni >> 1][(ni & 1) * 2]);
        buf++; if (buf >= NSTAGE) buf = 0;
    }

    // epilogue
    #pragma unroll
    for (int ni = 0; ni < 8; ni++) {
        const int cidx = n0 + wn0 + ni * 8 + (lane & 3) * 2;
        float b0 = 0.f, b1 = 0.f;
        if (BIAS) { b0 = bias[cidx]; b1 = bias[cidx + 1]; }
        float s0 = 0.f, s1 = 0.f, q0 = 0.f, q1 = 0.f;
        #pragma unroll
        for (int mi = 0; mi < 4; mi++) {
            const int r0 = m0 + wm0 + mi * 16 + (lane >> 2);
            #pragma unroll
            for (int half = 0; half < 2; half++) {
                const int r = r0 + half * 8;
                float v0 = acc[mi][ni][half * 2 + 0];
                float v1 = acc[mi][ni][half * 2 + 1];
                if (BIAS) { v0 += b0; v1 += b1; }
                if (RELU) { v0 = fmaxf(v0, 0.f); v1 = fmaxf(v1, 0.f); }
                if (BNS) {
                    s0 += v0; s1 += v1;
                    q0 = fmaf(v0, v0, q0); q1 = fmaf(v1, v1, q1);
                }
                if (SPLIT) {
                    if (cidx < 256) {
                        float2 f2 = make_float2(v0, v1);
                        *reinterpret_cast<float2*>(outF + (size_t)r * 256 + cidx) = f2;
                    } else {
                        __half2 hh = __halves2half2(__float2half(v0), __float2half(v1));
                        *reinterpret_cast<__half2*>(outH + (size_t)r * 256 + cidx - 256) = hh;
                    }
                } else {
                    if (OUTF) {
                        float2 f2 = make_float2(v0, v1);
                        *reinterpret_cast<float2*>(outF + (size_t)r * Nout + cidx) = f2;
                    }
                    if (OUTB) {
                        __half2 hh = __halves2half2(__float2half(v0), __float2half(v1));
                        *reinterpret_cast<__half2*>(outH + (size_t)r * Nout + cidx) = hh;
                    }
                }
            }
        }
        if (BNS) {
            // reduce over the 8 lanes covering this warp's 64 rows (stride-4 groups)
            #pragma unroll
            for (int off = 4; off < 32; off <<= 1) {
                s0 += __shfl_xor_sync(0xffffffffu, s0, off);
                s1 += __shfl_xor_sync(0xffffffffu, s1, off);
                q0 += __shfl_xor_sync(0xffffffffu, q0, off);
                q1 += __shfl_xor_sync(0xffffffffu, q1, off);
            }
            if ((lane >> 2) == 0) {
                const int seg = blockIdx.y * 2 + (wid & 1);
                bnp[seg * 512 + cidx]           = s0;
                bnp[seg * 512 + cidx + 1]       = s1;
                bnp[seg * 512 + 256 + cidx]     = q0;
                bnp[seg * 512 + 256 + cidx + 1] = q1;
            }
        }
    }
}

// ------------- ctx partial: per (chunk,h,b,path) K^T V over 512 rows --------
__global__ void __launch_bounds__(64)
ctx_partial_k(const __half* __restrict__ KV1, const __half* __restrict__ KV2,
              float* __restrict__ part)
{
    __shared__ float Ks[64][32];
    __shared__ float Vs[64][32];
    const int chunk = blockIdx.x, h = blockIdx.y, z = blockIdx.z;
    const int b = z & 15;
    const __half* KV = (z < 16) ? KV1 : KV2;
    const int t = threadIdx.x, lane = t & 31, w = t >> 5;
    const __half* base = KV + (size_t)b * HWn * 512;
    const int d0 = (t >> 3) * 4, e0 = (t & 7) * 4;
    float acc[4][4] = {};
    for (int nb = 0; nb < 512; nb += 64) {
        const int row0 = chunk * 512 + nb;
        for (int r = w; r < 64; r += 2) {
            const __half* rp = base + (size_t)(row0 + r) * 512 + h * 32;
            Ks[r][lane] = __half2float(rp[lane]);
            Vs[r][lane] = __half2float(rp[256 + lane]);
        }
        __syncthreads();
        #pragma unroll 8
        for (int n = 0; n < 64; n++) {
            float4 k4 = *reinterpret_cast<float4*>(&Ks[n][d0]);
            float4 v4 = *reinterpret_cast<float4*>(&Vs[n][e0]);
            const float kk[4] = {k4.x, k4.y, k4.z, k4.w};
            const float vv[4] = {v4.x, v4.y, v4.z, v4.w};
            #pragma unroll
            for (int i = 0; i < 4; i++)
                #pragma unroll
                for (int j = 0; j < 4; j++)
                    acc[i][j] = fmaf(kk[i], vv[j], acc[i][j]);
        }
        __syncthreads();
    }
    float* p = part + ((size_t)(z * NHn + h) * 8 + chunk) * 1024;
    #pragma unroll
    for (int i = 0; i < 4; i++)
        #pragma unroll
        for (int j = 0; j < 4; j++)
            p[(d0 + i) * 32 + e0 + j] = acc[i][j];
}

// ------------- ctx finalize: sum partials, scale, softmax over d -----------
__global__ void ctx_final_k(const float* __restrict__ part, float* __restrict__ ctx1,
                            float* __restrict__ ctx2)
{
    __shared__ float S[32][33];
    const int bhg = blockIdx.x;        // [0,256): path*128 + bh
    float* ctx = (bhg < 128) ? ctx1 : ctx2;
    const int bh = bhg & 127;
    const int t  = threadIdx.x;
    const float* p = part + (size_t)bhg * 8 * 1024;
    for (int idx = t; idx < 1024; idx += 256) {
        float s = 0.f;
        #pragma unroll
        for (int c = 0; c < 8; c++) s += p[c * 1024 + idx];
        S[idx >> 5][idx & 31] = s * SCALE;
    }
    __syncthreads();
    if (t < 32) {
        float mx = -1e30f;
        #pragma unroll
        for (int d = 0; d < 32; d++) mx = fmaxf(mx, S[d][t]);
        float e[32], sum = 0.f;
        #pragma unroll
        for (int d = 0; d < 32; d++) { e[d] = expf(S[d][t] - mx); sum += e[d]; }
        const float inv = 1.f / sum;
        float* o = ctx + (size_t)bh * 1024;
        #pragma unroll
        for (int d = 0; d < 32; d++) o[d * 32 + t] = e[d] * inv;
    }
}

// ------------- build per-batch ep "M" weights: M[o, j] (fp16) ---------------
__global__ void __launch_bounds__(256)
ctxw_k(const float* __restrict__ ctx1, const float* __restrict__ ctx2,
       const float* __restrict__ ep1_w, const float* __restrict__ ep2_w,
       __half* __restrict__ mw)
{
    __shared__ float cs[8192];
    const int z = blockIdx.x;                 // path*16 + b
    const int og = blockIdx.y;                // o-group: 16 o values
    const int path = z >> 4;
    const int b = z & 15;
    const float* ctx = path ? ctx1 : ctx2;
    const float* epw = path ? ep2_w : ep1_w;
    const int j = threadIdx.x;                // u-column 0..255
    for (int i = j; i < 8192; i += 256)
        cs[i] = ctx[(size_t)b * 8192 + i];
    __syncthreads();
    const int h = j >> 5, d = j & 31;
    float c[32];
    #pragma unroll
    for (int e = 0; e < 32; e++) c[e] = cs[h * 1024 + d * 32 + e];
    __half* oh = mw + (size_t)z * 65536;
    #pragma unroll
    for (int oo = 0; oo < 16; oo++) {
        const int o = og * 16 + oo;
        const float* wr = epw + (size_t)o * 512 + 256 + h * 32;
        float a = 0.f;
        #pragma unroll
        for (int e = 0; e < 32; e++) a = fmaf(c[e], __ldg(wr + e), a);
        oh[o * 256 + j] = __float2half(a);
    }
}

// ------------- LayerNorm: MRG[:, mco..] = LN(T + EP)*g + b (fp16 out) --------
__global__ void __launch_bounds__(256)
ln_k(const __half* __restrict__ T1, const __half* __restrict__ T2,
     const float* __restrict__ EP1, const float* __restrict__ EP2,
     const float* __restrict__ g1, const float* __restrict__ b1,
     const float* __restrict__ g2, const float* __restrict__ b2,
     __half* __restrict__ MH)
{
    const int path = blockIdx.y;
    const __half* Th = path ? T2 : T1;
    const float* EP = path ? EP2 : EP1;
    const float* g  = path ? g2 : g1;
    const float* be = path ? b2 : b1;
    const int mco = path * 256;
    const int w    = blockIdx.x * 8 + (threadIdx.x >> 5);
    const int lane = threadIdx.x & 31;
    const __half* th = Th + (size_t)w * 256;
    const float* er = EP + (size_t)w * 256;
    float v[8], sum = 0.f, sq = 0.f;
    #pragma unroll
    for (int i = 0; i < 8; i++) {
        const int c = lane + i * 32;
        const float x = __half2float(th[c]) + er[c];
        v[i] = x; sum += x; sq += x * x;
    }
    #pragma unroll
    for (int o = 16; o; o >>= 1) {
        sum += __shfl_xor_sync(0xffffffffu, sum, o);
        sq  += __shfl_xor_sync(0xffffffffu, sq,  o);
    }
    const float mean = sum * (1.f / 256.f);
    const float var  = sq * (1.f / 256.f) - mean * mean;
    const float rs   = rsqrtf(var + EPSF);
    const size_t ob = (size_t)w * 512 + mco;
    #pragma unroll
    for (int i = 0; i < 8; i++) {
        const int c = lane + i * 32;
        MH[ob + c] = __float2half((v[i] - mean) * rs * g[c] + be[c]);
    }
}

// ------------- 3x3 depthwise conv on fp16 [M,256] + bias + relu (fp16 out) ---
__global__ void __launch_bounds__(256)
dw_k(const __half* __restrict__ X, const float* __restrict__ w9,
     const float* __restrict__ db, __half* __restrict__ Y)
{
    __shared__ float s[18 * 18 * 32];
    const int cc   = blockIdx.x;
    const int tile = blockIdx.y;
    const int b    = blockIdx.z;
    const int ty0 = (tile >> 2) * 16, tx0 = (tile & 3) * 16;
    const int c0 = cc * 32;
    const int tid = threadIdx.x;
    for (int i = tid; i < 18 * 18 * 32; i += 256) {
        const int c = i & 31;
        const int sp = i >> 5;
        const int x = sp % 18 - 1 + tx0;
        const int y = sp / 18 - 1 + ty0;
        float v = 0.f;
        if (x >= 0 && x < 64 && y >= 0 && y < 64)
            v = __half2float(X[(size_t)(b * 4096 + y * 64 + x) * 256 + c0 + c]);
        s[i] = v;
    }
    const int c = tid & 31;
    float kr[9];
    #pragma unroll
    for (int j = 0; j < 9; j++) kr[j] = w9[(c0 + c) * 9 + j];
    const float bb = db[c0 + c];
    __syncthreads();
    for (int o = tid; o < 8192; o += 256) {
        const int sp = o >> 5;
        const int x = sp & 15, y = sp >> 4;
        float a = 0.f;
        #pragma unroll
        for (int dy = 0; dy < 3; dy++)
            #pragma unroll
            for (int dx = 0; dx < 3; dx++)
                a = fmaf(s[((y + dy) * 18 + (x + dx)) * 32 + c], kr[dy * 3 + dx], a);
        a = fmaxf(a + bb, 0.f);
        const size_t idx = (size_t)(b * 4096 + (ty0 + y) * 64 + tx0 + x) * 256 + c0 + c;
        Y[idx] = __float2half(a);
    }
}

// ------------- bn finalize from partials (1024 threads, 4-way split) ---------
__global__ void __launch_bounds__(1024)
bn_fin_k(const float* __restrict__ part, int nseg,
         const float* __restrict__ g, const float* __restrict__ be,
         float* __restrict__ sc, float* __restrict__ sh)
{
    __shared__ float ss[4][256];
    __shared__ float sq[4][256];
    const int c = threadIdx.x & 255;
    const int q = threadIdx.x >> 8;     // 0..3
    float s = 0.f, qq = 0.f;
    for (int seg = q; seg < nseg; seg += 4) {
        s  += part[seg * 512 + c];
        qq += part[seg * 512 + 256 + c];
    }
    ss[q][c] = s; sq[q][c] = qq;
    __syncthreads();
    if (q == 0) {
        s  = ss[0][c] + ss[1][c] + ss[2][c] + ss[3][c];
        qq = sq[0][c] + sq[1][c] + sq[2][c] + sq[3][c];
        const float inv = 1.f / 65536.f;
        const float m   = s * inv;
        const float var = qq * inv - m * m;
        const float scv = g[c] * rsqrtf(var + EPSF);
        sc[c] = scv;
        sh[c] = be[c] - m * scv;
    }
}

// ------------- F = RES + E*sc + sh, fused with F column partials -------------
__global__ void __launch_bounds__(256)
addbn_bn_k(const float* __restrict__ RES, const float* __restrict__ E,
           const float* __restrict__ sc, const float* __restrict__ sh,
           float* __restrict__ F, float* __restrict__ part)
{
    const int seg = blockIdx.x;          // 256 segments of 256 rows
    const int c   = threadIdx.x;
    const float s = sc[c], hh = sh[c];
    const size_t base = (size_t)seg * 256 * 256;
    float su = 0.f, q = 0.f;
    #pragma unroll 4
    for (int r = 0; r < 256; r++) {
        const size_t idx = base + (size_t)r * 256 + c;
        const float f = fmaf(E[idx], s, RES[idx] + hh);
        F[idx] = f;
        su += f;
        q = fmaf(f, f, q);
    }
    part[seg * 512 + c] = su;
    part[seg * 512 + 256 + c] = q;
}

// ------------- final: out NCHW = bn2(F) via transpose ------------------------
__global__ void bn_final_k(const float* __restrict__ F, const float* __restrict__ sc,
                           const float* __restrict__ sh, float* __restrict__ O)
{
    __shared__ float s[32][33];
    const int b  = blockIdx.z;
    const int c0 = blockIdx.y * 32;
    const int n0 = blockIdx.x * 32;
    const int tx = threadIdx.x, ty = threadIdx.y;
    #pragma unroll
    for (int i = 0; i < 32; i += 8)
        s[ty + i][tx] = F[((size_t)(b * 4096 + n0 + ty + i)) * 256 + c0 + tx];
    __syncthreads();
    #pragma unroll
    for (int i = 0; i < 32; i += 8) {
        const int c = c0 + ty + i;
        O[((size_t)(b * 256 + c)) * 4096 + n0 + tx] = s[tx][ty + i] * sc[c] + sh[c];
    }
}

// ===========================================================================
extern "C" void kernel_launch(void* const* d_in, const int* in_sizes, int n_in,
                              void* d_out, int out_size)
{
    (void)in_sizes; (void)n_in; (void)out_size;
    const float* x1    = (const float*)d_in[0];
    const float* x2    = (const float*)d_in[1];
    const float* cp1_w = (const float*)d_in[2];
    const float* cp1_b = (const float*)d_in[3];
    const float* cp2_w = (const float*)d_in[4];
    const float* cp2_b = (const float*)d_in[5];
    const float* kv1_w = (const float*)d_in[6];
    const float* kv2_w = (const float*)d_in[7];
    const float* ep1_w = (const float*)d_in[8];
    const float* ep1_b = (const float*)d_in[9];
    const float* ep2_w = (const float*)d_in[10];
    const float* ep2_b = (const float*)d_in[11];
    const float* ln1_g = (const float*)d_in[12];
    const float* ln1_b = (const float*)d_in[13];
    const float* ln2_g = (const float*)d_in[14];
    const float* ln2_b = (const float*)d_in[15];
    const float* res_w = (const float*)d_in[16];
    const float* ce1_w = (const float*)d_in[17];
    const float* ce1_b = (const float*)d_in[18];
    const float* dw_w  = (const float*)d_in[19];
    const float* dw_b  = (const float*)d_in[20];
    const float* ce3_w = (const float*)d_in[21];
    const float* ce3_b = (const float*)d_in[22];
    const float* bn1_g = (const float*)d_in[23];
    const float* bn1_b = (const float*)d_in[24];
    const float* bn2_g = (const float*)d_in[25];
    const float* bn2_b = (const float*)d_in[26];

    float *EP1, *EP2, *RES, *E, *F;
    float *PART, *CTX1, *CTX2, *CB, *BNP, *SC1, *SH1, *SC2, *SH2;
    __half *T1, *T2, *P1, *P2, *KV1, *KV2, *MRG, *CE, *DW, *WH, *EPY, *MW;
    cudaGetSymbolAddress((void**)&T1,  g_T1);
    cudaGetSymbolAddress((void**)&T2,  g_T2);
    cudaGetSymbolAddress((void**)&P1,  g_P1);
    cudaGetSymbolAddress((void**)&P2,  g_P2);
    cudaGetSymbolAddress((void**)&KV1, g_KV1);
    cudaGetSymbolAddress((void**)&KV2, g_KV2);
    cudaGetSymbolAddress((void**)&EP1, g_EP1);
    cudaGetSymbolAddress((void**)&EP2, g_EP2);
    cudaGetSymbolAddress((void**)&MRG, g_MRG);
    cudaGetSymbolAddress((void**)&RES, g_RES);
    cudaGetSymbolAddress((void**)&CE,  g_CE);
    cudaGetSymbolAddress((void**)&DW,  g_DW);
    cudaGetSymbolAddress((void**)&E,   g_E);
    cudaGetSymbolAddress((void**)&F,   g_F);
    cudaGetSymbolAddress((void**)&WH,  g_WH);
    cudaGetSymbolAddress((void**)&EPY, g_EPY);
    cudaGetSymbolAddress((void**)&MW,  g_MW);
    cudaGetSymbolAddress((void**)&PART, g_PART);
    cudaGetSymbolAddress((void**)&CTX1, g_CTX1);
    cudaGetSymbolAddress((void**)&CTX2, g_CTX2);
    cudaGetSymbolAddress((void**)&CB,  g_CB);
    cudaGetSymbolAddress((void**)&BNP, g_BNP);
    cudaGetSymbolAddress((void**)&SC1, g_SC1);
    cudaGetSymbolAddress((void**)&SH1, g_SH1);
    cudaGetSymbolAddress((void**)&SC2, g_SC2);
    cudaGetSymbolAddress((void**)&SH2, g_SH2);

    cudaFuncSetAttribute(gemm_tc<true,  true,  false, true , false, false, true , false>,
                         cudaFuncAttributeMaxDynamicSharedMemorySize, DYN_SMEM);
    cudaFuncSetAttribute(gemm_tc<false, false, false, true , false, false, true , false>,
                         cudaFuncAttributeMaxDynamicSharedMemorySize, DYN_SMEM);
    cudaFuncSetAttribute(gemm_tc<true,  false, true,  false, true , false, true , false>,
                         cudaFuncAttributeMaxDynamicSharedMemorySize, DYN_SMEM);
    cudaFuncSetAttribute(gemm_tc<true,  false, false, false, false, true , false, false>,
                         cudaFuncAttributeMaxDynamicSharedMemorySize, DYN_SMEM);
    cudaFuncSetAttribute(gemm_tc<true,  false, true,  false, false, false, false, true >,
                         cudaFuncAttributeMaxDynamicSharedMemorySize, DYN_SMEM);

    // weight slots in WH (851968 total)
    const size_t oCP1 = 0, oCP2 = 131072, oKV1 = 262144, oKV2 = 393216;
    const size_t oRC = 524288, oCE3 = 786432;
    WsplitArgs wa;
    wa.src[0] = cp1_w; wa.src[1] = cp2_w; wa.src[2] = kv1_w; wa.src[3] = kv2_w;
    wa.src[4] = res_w; wa.src[5] = ce1_w; wa.src[6] = ce3_w;

    // merged preamble: weight converts + ep strided + bias concat
    preamble_k<<<3842, 256>>>(wa, ep1_w, ep2_w, ce1_b, WH, EPY, CB);
    transpose_split_k<<<dim3(128, 8, 32), dim3(32, 8)>>>(x1, x2, T1, T2);

    // CrossPath pair: P = relu(T @ cp_w^T + b) -> fp16
    gemm_tc<true, true, false, true, false, false, true, false>
        <<<dim3(4, 512, 2), 128, DYN_SMEM>>>(
        T1, 256, WH + oCP1, nullptr, cp1_b, nullptr, P1,
        T2, WH + oCP2, nullptr, cp2_b, nullptr, P2, nullptr, 256, 512);

    // KV pair: KV = u @ kv_w^T -> fp16
    gemm_tc<false, false, false, true, false, false, true, false>
        <<<dim3(4, 512, 2), 128, DYN_SMEM>>>(
        P1 + 256, 512, WH + oKV1, nullptr, nullptr, nullptr, KV1,
        P2 + 256, WH + oKV2, nullptr, nullptr, nullptr, KV2, nullptr, 256, 512);

    // ctx = softmax_d(scale * K^T V), both paths
    ctx_partial_k<<<dim3(8, 8, 32), 64>>>(KV1, KV2, PART);
    ctx_final_k<<<256, 256>>>(PART, CTX1, CTX2);

    // per-batch M weights for the fused ep GEMM (cross-wired)
    ctxw_k<<<dim3(32, 16), 256>>>(CTX1, CTX2, ep1_w, ep2_w, MW);

    // EP pair: EP = y @ W1 + u @ M_b + bias (dual-source B)
    gemm_tc<true, false, true, false, true, false, true, false>
        <<<dim3(2, 512, 2), 128, DYN_SMEM>>>(
        P1, 512, EPY, MW, ep1_b, EP1, nullptr,
        P2, EPY + 65536, MW + 16 * 65536, ep2_b, EP2, nullptr, nullptr, 512, 256);

    // LN both paths -> MRG fp16
    ln_k<<<dim3(8192, 2), 256>>>(T1, T2, EP1, EP2,
                                 ln1_g, ln1_b, ln2_g, ln2_b, MRG);

    // res|ce1 concatenated GEMM -> RES fp32 [M,256] + CE fp16 [M,256]
    gemm_tc<true, false, false, false, false, true, false, false>
        <<<dim3(4, 512), 128, DYN_SMEM>>>(
        MRG, 512, WH + oRC, nullptr, CB, RES, CE,
        nullptr, nullptr, nullptr, nullptr, nullptr, nullptr, nullptr, 512, 512);

    // 3x3 depthwise (+bias+relu) on fp16 CE -> DW fp16
    dw_k<<<dim3(8, 16, 16), 256>>>(CE, dw_w, dw_b, DW);

    // ce3 GEMM -> E fp32, bn1 column partials via warp shuffles (no atomics)
    gemm_tc<true, false, true, false, false, false, false, true>
        <<<dim3(2, 512), 128, DYN_SMEM>>>(
        DW, 256, WH + oCE3, nullptr, ce3_b, E, nullptr,
        nullptr, nullptr, nullptr, nullptr, nullptr, nullptr, BNP, 256, 256);

    // bn1 finalize -> fused residual add + bn1 apply + bn2 partials -> bn2 -> out
    bn_fin_k<<<1, 1024>>>(BNP, 1024, bn1_g, bn1_b, SC1, SH1);
    addbn_bn_k<<<256, 256>>>(RES, E, SC1, SH1, F, BNP);
    bn_fin_k<<<1, 1024>>>(BNP, 256, bn2_g, bn2_b, SC2, SH2);
    bn_final_k<<<dim3(128, 8, 16), dim3(32, 8)>>>(F, SC2, SH2, (float*)d_out);
}